// round 6
// baseline (speedup 1.0000x reference)
#include <cuda_runtime.h>
#include <cuda_fp16.h>
#include <math.h>
#include <stdint.h>

#define NB 8
#define NT 2048
#define NC 512
#define NK 512
#define SCALE 0.044194173824159216f  // 1/sqrt(512)

// Scratch (device globals: allocation-free per harness rules)
static __device__ __half g_xh[(size_t)NB * NT * NC];
static __device__ __half g_wh[3 * 512 * 512];
static __device__ __half g_qh[(size_t)NB * NT * NK];
static __device__ __half g_kh[(size_t)NB * NT * NK];
static __device__ __half g_vh[(size_t)NB * NT * NK];
static __device__ __half g_vT[(size_t)NB * NK * NT];   // [b*512+n][s]
static __device__ float  g_S [(size_t)NB * NT * NT];   // fp32 scores
static __device__ __half g_P [(size_t)NB * NT * NT];   // fp16 probs

// ---------------------------------------------------------------------------
// helpers
// ---------------------------------------------------------------------------
__device__ __forceinline__ void cpa16(void* dst_smem, const void* src) {
    unsigned s = (unsigned)__cvta_generic_to_shared(dst_smem);
    asm volatile("cp.async.ca.shared.global [%0], [%1], 16;\n" :: "r"(s), "l"(src));
}
#define CP_COMMIT() asm volatile("cp.async.commit_group;\n" ::: "memory")
#define CP_WAIT0()  asm volatile("cp.async.wait_group 0;\n" ::: "memory")
#define CP_WAIT1()  asm volatile("cp.async.wait_group 1;\n" ::: "memory")

// f16 in, f16 accumulate (chained): D,C = 2 regs (4 halves)
#define MMA_F16(d, a, b)                                                    \
    asm volatile(                                                           \
        "mma.sync.aligned.m16n8k16.row.col.f16.f16.f16.f16 "                \
        "{%0,%1},{%2,%3,%4,%5},{%6,%7},{%0,%1};\n"                          \
        : "+r"((d)[0]), "+r"((d)[1])                                        \
        : "r"((a)[0]), "r"((a)[1]), "r"((a)[2]), "r"((a)[3]),               \
          "r"((b)[0]), "r"((b)[1]))

// Stage layout: tile = 128 rows x 32 halfs (64B data), row stride 80B.
#define ROWB     80
#define A_BYTES  10240
#define STAGE_B  20480

// 512 threads: each stages 2 x 16B chunks (one per tile)
__device__ __forceinline__ void stage_issue(
    char* st, const __half* Ag, size_t asr,
    const __half* Bg, size_t bsr, int k0, int tid)
{
    const int r = tid >> 2;
    const int q = tid & 3;
    cpa16(st + r * ROWB + q * 16,           Ag + (size_t)r * asr + k0 + q * 8);
    cpa16(st + A_BYTES + r * ROWB + q * 16, Bg + (size_t)r * bsr + k0 + q * 8);
    CP_COMMIT();
}

// one 128x128x32 buffer: 2 k16 steps; 16 warps, warp tile 64x16 (2m x 8n)
__device__ __forceinline__ void compute_buf(
    const char* smA, const char* smB,
    int wm, int wn, int gid, int tig, uint32_t hacc[4][2][2])
{
    #pragma unroll
    for (int ks = 0; ks < 2; ks++) {
        const int kb = (ks * 16 + 2 * tig) * 2;
        uint32_t af[4][4];
        #pragma unroll
        for (int mt = 0; mt < 4; mt++) {
            const char* base = smA + (wm + mt * 16 + gid) * ROWB + kb;
            af[mt][0] = *(const uint32_t*)(base);
            af[mt][1] = *(const uint32_t*)(base + 8 * ROWB);
            af[mt][2] = *(const uint32_t*)(base + 16);
            af[mt][3] = *(const uint32_t*)(base + 8 * ROWB + 16);
        }
        uint32_t bf[2][2];
        #pragma unroll
        for (int nt = 0; nt < 2; nt++) {
            const char* bb = smB + (wn + nt * 8 + gid) * ROWB + kb;
            bf[nt][0] = *(const uint32_t*)(bb);
            bf[nt][1] = *(const uint32_t*)(bb + 16);
        }
        #pragma unroll
        for (int mt = 0; mt < 4; mt++)
            #pragma unroll
            for (int nt = 0; nt < 2; nt++)
                MMA_F16(hacc[mt][nt], af[mt], bf[nt]);
    }
}

__device__ __forceinline__ void fold_acc(uint32_t hacc[4][2][2], float acc[4][2][4])
{
    #pragma unroll
    for (int mt = 0; mt < 4; mt++)
        #pragma unroll
        for (int nt = 0; nt < 2; nt++) {
            float2 f0 = __half22float2(*(__half2*)&hacc[mt][nt][0]);
            float2 f1 = __half22float2(*(__half2*)&hacc[mt][nt][1]);
            acc[mt][nt][0] += f0.x; acc[mt][nt][1] += f0.y;
            acc[mt][nt][2] += f1.x; acc[mt][nt][3] += f1.y;
            hacc[mt][nt][0] = 0; hacc[mt][nt][1] = 0;
        }
}

// 3-stage pipelined NT GEMM (both operands k-major fp16), KT even.
// fp16 accumulate chains folded to fp32 masters every 2 iters (K=64).
__device__ __forceinline__ void gemm_loop(
    const __half* Ag, size_t asr,
    const __half* Bg, size_t bsr,
    int KT, float acc[4][2][4])
{
    extern __shared__ char dsm[];
    const int tid  = threadIdx.x;
    const int wid  = tid >> 5;
    const int lane = tid & 31;
    const int gid  = lane >> 2;
    const int tig  = lane & 3;
    const int wm   = (wid & 1) * 64;
    const int wn   = (wid >> 1) * 16;

    uint32_t hacc[4][2][2];
    #pragma unroll
    for (int mt = 0; mt < 4; mt++)
        #pragma unroll
        for (int nt = 0; nt < 2; nt++) { hacc[mt][nt][0] = 0; hacc[mt][nt][1] = 0; }

    stage_issue(dsm,           Ag, asr, Bg, bsr, 0,  tid);
    stage_issue(dsm + STAGE_B, Ag, asr, Bg, bsr, 32, tid);

    for (int i = 0; i < KT; i++) {
        if (i + 2 < KT) CP_WAIT1(); else CP_WAIT0();
        __syncthreads();
        if (i + 2 < KT) {
            char* st = dsm + ((i + 2) % 3) * STAGE_B;
            stage_issue(st, Ag, asr, Bg, bsr, (i + 2) * 32, tid);
        }
        const char* sb = dsm + (i % 3) * STAGE_B;
        compute_buf(sb, sb + A_BYTES, wm, wn, gid, tig, hacc);
        if (i & 1) fold_acc(hacc, acc);
        __syncthreads();
    }
}

// ---------------------------------------------------------------------------
// conversion kernels
// ---------------------------------------------------------------------------
__global__ void __launch_bounds__(256) convcopy_x(
    const float* __restrict__ x, float* __restrict__ out)
{
    size_t i4 = (size_t)blockIdx.x * blockDim.x + threadIdx.x;  // 2097152 total
    float4 a = ((const float4*)x)[i4];
    size_t row = i4 / 128;
    size_t c4  = i4 % 128;
    ((float4*)out)[row * 256 + c4] = a;                      // out[..., 0:512] = x
    __half2 h0 = __floats2half2_rn(a.x, a.y);
    __half2 h1 = __floats2half2_rn(a.z, a.w);
    ((__half2*)g_xh)[i4 * 2]     = h0;
    ((__half2*)g_xh)[i4 * 2 + 1] = h1;
}

__global__ void __launch_bounds__(256) convw_kernel(
    const float* __restrict__ Wq, const float* __restrict__ Wk,
    const float* __restrict__ Wv)
{
    size_t i4 = (size_t)blockIdx.x * blockDim.x + threadIdx.x;  // 196608 total
    int which = (int)(i4 >> 16);
    size_t loc = i4 & 65535;
    const float* src = (which == 0) ? Wq : (which == 1) ? Wk : Wv;
    float4 a = ((const float4*)src)[loc];
    ((__half2*)g_wh)[i4 * 2]     = __floats2half2_rn(a.x, a.y);
    ((__half2*)g_wh)[i4 * 2 + 1] = __floats2half2_rn(a.z, a.w);
}

// ---------------------------------------------------------------------------
// Kernel: q/k/v = x @ W^T + b  (fp16 out)
// ---------------------------------------------------------------------------
__global__ void __launch_bounds__(512, 1) qkv_kernel(
    const float* __restrict__ bq, const float* __restrict__ bk,
    const float* __restrict__ bv)
{
    const int which = blockIdx.z;
    const float* bias = (which == 0) ? bq : (which == 1) ? bk : bv;
    __half* outp = (which == 0) ? g_qh : (which == 1) ? g_kh : g_vh;

    const int m0 = blockIdx.y * 128;
    const int n0 = blockIdx.x * 128;

    float acc[4][2][4] = {};
    gemm_loop(g_xh + (size_t)m0 * NC, NC,
              g_wh + (size_t)which * 512 * 512 + (size_t)n0 * NC, NC,
              NC / 32, acc);

    const int tid = threadIdx.x, wid = tid >> 5, lane = tid & 31;
    const int gid = lane >> 2, tig = lane & 3;
    const int wm = (wid & 1) * 64, wn = (wid >> 1) * 16;

    #pragma unroll
    for (int mt = 0; mt < 4; mt++) {
        #pragma unroll
        for (int nt = 0; nt < 2; nt++) {
            int m = m0 + wm + mt * 16 + gid;
            int n = n0 + wn + nt * 8 + 2 * tig;
            float b0 = bias[n], b1 = bias[n + 1];
            __half2 h0 = __floats2half2_rn(acc[mt][nt][0] + b0, acc[mt][nt][1] + b1);
            __half2 h1 = __floats2half2_rn(acc[mt][nt][2] + b0, acc[mt][nt][3] + b1);
            *(__half2*)(outp + (size_t)m * NK + n) = h0;
            *(__half2*)(outp + (size_t)(m + 8) * NK + n) = h1;
        }
    }
}

// ---------------------------------------------------------------------------
// Kernel: transpose V (fp16) -> g_vT[b*512+n][s]; tile 32 s x 64 n
// ---------------------------------------------------------------------------
__global__ void __launch_bounds__(256) vtrans_kernel()
{
    __shared__ __half ts[32][66];
    const int b  = blockIdx.z;
    const int n0 = blockIdx.x * 64;
    const int s0 = blockIdx.y * 32;
    const int tid = threadIdx.x;

    {
        const int cu = tid & 31;
        const int r0 = tid >> 5;
        #pragma unroll
        for (int j = 0; j < 4; j++) {
            int r = r0 + 8 * j;
            uint32_t v = *(const uint32_t*)(g_vh + ((size_t)(b * NT + s0 + r)) * NK + n0 + cu * 2);
            *(uint32_t*)&ts[r][cu * 2] = v;
        }
    }
    __syncthreads();
    {
        const int cw = tid & 15;
        const int rn0 = tid >> 4;
        #pragma unroll
        for (int j = 0; j < 4; j++) {
            int n = rn0 + 16 * j;
            __half2 p;
            p.x = ts[2 * cw][n];
            p.y = ts[2 * cw + 1][n];
            *(__half2*)(g_vT + ((size_t)(b * NK + n0 + n)) * NT + s0 + 2 * cw) = p;
        }
    }
}

// ---------------------------------------------------------------------------
// Kernel: S = (q @ k^T) * SCALE, lower-triangle tiles only (fp32 out)
// ---------------------------------------------------------------------------
__global__ void __launch_bounds__(512, 1) scores_kernel()
{
    const int b = blockIdx.y;
    int xi = blockIdx.x;
    int qt = (int)((sqrtf(8.0f * xi + 1.0f) - 1.0f) * 0.5f);
    while ((qt + 1) * (qt + 2) / 2 <= xi) qt++;
    while (qt * (qt + 1) / 2 > xi) qt--;
    const int st = xi - qt * (qt + 1) / 2;

    const int m0 = qt * 128;
    const int n0 = st * 128;

    float acc[4][2][4] = {};
    gemm_loop(g_qh + ((size_t)b * NT + m0) * NK, NK,
              g_kh + ((size_t)b * NT + n0) * NK, NK,
              NK / 32, acc);

    float* S = g_S + (size_t)b * NT * NT;
    const int tid = threadIdx.x, wid = tid >> 5, lane = tid & 31;
    const int gid = lane >> 2, tig = lane & 3;
    const int wm = (wid & 1) * 64, wn = (wid >> 1) * 16;

    #pragma unroll
    for (int mt = 0; mt < 4; mt++) {
        #pragma unroll
        for (int nt = 0; nt < 2; nt++) {
            int m = m0 + wm + mt * 16 + gid;
            int n = n0 + wn + nt * 8 + 2 * tig;
            float2 v0 = { acc[mt][nt][0] * SCALE, acc[mt][nt][1] * SCALE };
            float2 v1 = { acc[mt][nt][2] * SCALE, acc[mt][nt][3] * SCALE };
            *(float2*)(S + (size_t)m * NT + n) = v0;
            *(float2*)(S + (size_t)(m + 8) * NT + n) = v1;
        }
    }
}

// ---------------------------------------------------------------------------
// Kernel: column softmax stats (online) + write P (fp16)
// ---------------------------------------------------------------------------
__global__ void __launch_bounds__(256) colstats_kernel()
{
    const int b = blockIdx.y;
    const int cc = threadIdx.x & 31;
    const int rl = threadIdx.x >> 5;     // 0..7
    const int col = blockIdx.x * 32 + cc;
    const float* S = g_S + (size_t)b * NT * NT;
    __half* P = g_P + (size_t)b * NT * NT;

    __shared__ float redm[8][32];
    __shared__ float redz[8][32];

    const int qstart = (col & ~7) + rl;

    float m = -INFINITY, z = 0.f;
    for (int q = qstart; q < NT; q += 8) {
        if (q >= col) {
            float v = S[(size_t)q * NT + col];
            if (v > m) { z = z * __expf(m - v) + 1.f; m = v; }
            else       { z += __expf(v - m); }
        }
    }
    redm[rl][cc] = m;
    redz[rl][cc] = z;
    __syncthreads();
    if (rl == 0) {
        float M = m;
        #pragma unroll
        for (int r = 1; r < 8; r++) M = fmaxf(M, redm[r][cc]);
        float Z = 0.f;
        #pragma unroll
        for (int r = 0; r < 8; r++) Z += redz[r][cc] * __expf(redm[r][cc] - M);
        redm[0][cc] = M;
        redz[0][cc] = 1.f / Z;
    }
    __syncthreads();
    const float cm  = redm[0][cc];
    const float ciz = redz[0][cc];

    const int qb = (col & ~127) + rl;
    for (int q = qb; q < NT; q += 8) {
        float p = 0.f;
        if (q >= col)
            p = __expf(S[(size_t)q * NT + col] - cm) * ciz;
        P[(size_t)q * NT + col] = __float2half(p);
    }
}

// ---------------------------------------------------------------------------
// Kernel: attn = P @ V (B = g_vT), triangular k-range
// ---------------------------------------------------------------------------
__global__ void __launch_bounds__(512, 1) attnv_kernel(float* __restrict__ out)
{
    const int b  = blockIdx.z;
    const int qt = gridDim.y - 1 - blockIdx.y;  // big tiles first
    const int n0 = blockIdx.x * 128;
    const int m0 = qt * 128;
    const int KT = 4 * (qt + 1);

    float acc[4][2][4] = {};
    gemm_loop(g_P  + ((size_t)b * NT + m0) * NT, NT,
              g_vT + ((size_t)b * NK + n0) * NT, NT,
              KT, acc);

    const int tid = threadIdx.x, wid = tid >> 5, lane = tid & 31;
    const int gid = lane >> 2, tig = lane & 3;
    const int wm = (wid & 1) * 64, wn = (wid >> 1) * 16;

    #pragma unroll
    for (int mt = 0; mt < 4; mt++) {
        #pragma unroll
        for (int nt = 0; nt < 2; nt++) {
            int q = m0 + wm + mt * 16 + gid;
            int n = n0 + wn + nt * 8 + 2 * tig;
            float2 v0 = { acc[mt][nt][0], acc[mt][nt][1] };
            float2 v1 = { acc[mt][nt][2], acc[mt][nt][3] };
            *(float2*)(out + ((size_t)b * NT + q) * 1024 + 512 + n) = v0;
            *(float2*)(out + ((size_t)b * NT + q + 8) * 1024 + 512 + n) = v1;
        }
    }
}

// ---------------------------------------------------------------------------
extern "C" void kernel_launch(void* const* d_in, const int* in_sizes, int n_in,
                              void* d_out, int out_size)
{
    const float* x  = (const float*)d_in[0];
    const float* Wq = (const float*)d_in[1];
    const float* bq = (const float*)d_in[2];
    const float* Wk = (const float*)d_in[3];
    const float* bk = (const float*)d_in[4];
    const float* Wv = (const float*)d_in[5];
    const float* bv = (const float*)d_in[6];
    float* out = (float*)d_out;

    const int dsmem = 3 * STAGE_B;  // 61440 B
    cudaFuncSetAttribute(qkv_kernel,    cudaFuncAttributeMaxDynamicSharedMemorySize, dsmem);
    cudaFuncSetAttribute(scores_kernel, cudaFuncAttributeMaxDynamicSharedMemorySize, dsmem);
    cudaFuncSetAttribute(attnv_kernel,  cudaFuncAttributeMaxDynamicSharedMemorySize, dsmem);

    convcopy_x<<<dim3(8192), 256>>>(x, out);
    convw_kernel<<<dim3(768), 256>>>(Wq, Wk, Wv);
    qkv_kernel<<<dim3(4, 128, 3), 512, dsmem>>>(bq, bk, bv);
    vtrans_kernel<<<dim3(8, 64, 8), 256>>>();
    scores_kernel<<<dim3(136, 8), 512, dsmem>>>();
    colstats_kernel<<<dim3(64, 8), 256>>>();
    attnv_kernel<<<dim3(4, 16, 8), 512, dsmem>>>(out);
}

// round 7
// speedup vs baseline: 1.4361x; 1.4361x over previous
#include <cuda_runtime.h>
#include <cuda_bf16.h>
#include <math.h>
#include <stdint.h>

#define NB 8
#define NT 2048
#define NC 512
#define NK 512
#define SCALE 0.044194173824159216f  // 1/sqrt(512)

// Scratch (device globals: allocation-free per harness rules)
static __device__ __nv_bfloat16 g_xb[(size_t)NB * NT * NC];
static __device__ __nv_bfloat16 g_wb[3 * 512 * 512];
static __device__ __nv_bfloat16 g_qb[(size_t)NB * NT * NK];
static __device__ __nv_bfloat16 g_kb[(size_t)NB * NT * NK];
static __device__ __nv_bfloat16 g_vb[(size_t)NB * NT * NK];
static __device__ __nv_bfloat16 g_vT[(size_t)NB * NK * NT];  // [b*512+n][s]
static __device__ float         g_S [(size_t)NB * NT * NT];  // fp32 scores
static __device__ __nv_bfloat16 g_P [(size_t)NB * NT * NT];  // bf16 probs

// ---------------------------------------------------------------------------
// helpers
// ---------------------------------------------------------------------------
__device__ __forceinline__ void cpa16(void* dst_smem, const void* src) {
    unsigned s = (unsigned)__cvta_generic_to_shared(dst_smem);
    asm volatile("cp.async.ca.shared.global [%0], [%1], 16;\n" :: "r"(s), "l"(src));
}
#define CP_COMMIT() asm volatile("cp.async.commit_group;\n" ::: "memory")
#define CP_WAIT0()  asm volatile("cp.async.wait_group 0;\n" ::: "memory")
#define CP_WAIT1()  asm volatile("cp.async.wait_group 1;\n" ::: "memory")

#define MMA_BF16(c, a, b0, b1)                                              \
    asm volatile(                                                           \
        "mma.sync.aligned.m16n8k16.row.col.f32.bf16.bf16.f32 "              \
        "{%0,%1,%2,%3},{%4,%5,%6,%7},{%8,%9},{%0,%1,%2,%3};\n"              \
        : "+f"((c)[0]), "+f"((c)[1]), "+f"((c)[2]), "+f"((c)[3])            \
        : "r"((a)[0]), "r"((a)[1]), "r"((a)[2]), "r"((a)[3]),               \
          "r"(b0), "r"(b1))

#define LDSM4(r, a)                                                         \
    asm volatile("ldmatrix.sync.aligned.m8n8.x4.shared.b16 "                \
                 "{%0,%1,%2,%3}, [%4];"                                     \
                 : "=r"((r)[0]), "=r"((r)[1]), "=r"((r)[2]), "=r"((r)[3])   \
                 : "r"(a))

// Tile: 128 rows x 64 bf16 = 128B/row, XOR-swizzled in 16B chunks.
#define TILE_B   16384
#define STAGE_B  32768   // A tile + B tile
#define NSTAGE   3

// stage one (A,B) 128x64 bf16 tile pair; 256 threads, 4 chunk-pairs each
__device__ __forceinline__ void stage_issue(
    char* st, const __nv_bfloat16* Ag, size_t asr,
    const __nv_bfloat16* Bg, size_t bsr, int k0, int tid)
{
    #pragma unroll
    for (int j = 0; j < 4; j++) {
        int idx = j * 256 + tid;       // 0..1023
        int row = idx >> 3;
        int ch  = idx & 7;
        int pch = ch ^ (row & 7);      // XOR swizzle (16B units)
        cpa16(st + row * 128 + pch * 16,          Ag + (size_t)row * asr + k0 + ch * 8);
        cpa16(st + TILE_B + row * 128 + pch * 16, Bg + (size_t)row * bsr + k0 + ch * 8);
    }
    CP_COMMIT();
}

// compute one 128x128x64 buffer: 4 k16 steps; 8 warps, warp tile 64x32
__device__ __forceinline__ void compute_buf(
    const char* smA, const char* smB,
    int wm, int wn, int lane, float acc[4][4][4])
{
    const int lr = lane & 15;      // row-within-16
    const int cg = lane >> 4;      // 0/1: which 16B chunk of the k16 group
    #pragma unroll
    for (int kg = 0; kg < 4; kg++) {
        uint32_t af[4][4];
        #pragma unroll
        for (int mt = 0; mt < 4; mt++) {
            int row = wm + mt * 16 + lr;
            int pch = (kg * 2 + cg) ^ (row & 7);
            uint32_t a = (uint32_t)__cvta_generic_to_shared(smA + row * 128 + pch * 16);
            LDSM4(af[mt], a);
        }
        uint32_t bq[2][4];
        #pragma unroll
        for (int pn = 0; pn < 2; pn++) {
            int row = wn + pn * 16 + lr;
            int pch = (kg * 2 + cg) ^ (row & 7);
            uint32_t a = (uint32_t)__cvta_generic_to_shared(smB + row * 128 + pch * 16);
            LDSM4(bq[pn], a);
        }
        #pragma unroll
        for (int mt = 0; mt < 4; mt++) {
            #pragma unroll
            for (int nt = 0; nt < 4; nt++) {
                const uint32_t* bp = bq[nt >> 1];
                uint32_t b0 = (nt & 1) ? bp[1] : bp[0];
                uint32_t b1 = (nt & 1) ? bp[3] : bp[2];
                MMA_BF16(acc[mt][nt], af[mt], b0, b1);
            }
        }
    }
}

// 3-stage pipelined NT GEMM (both operands k-major bf16). KT in k64 units.
__device__ __forceinline__ void gemm_loop(
    const __nv_bfloat16* Ag, size_t asr,
    const __nv_bfloat16* Bg, size_t bsr,
    int KT, float acc[4][4][4])
{
    extern __shared__ char dsm[];
    const int tid  = threadIdx.x;
    const int wid  = tid >> 5;
    const int lane = tid & 31;
    const int wm   = (wid & 1) * 64;
    const int wn   = (wid >> 1) * 32;

    stage_issue(dsm,           Ag, asr, Bg, bsr, 0,  tid);
    stage_issue(dsm + STAGE_B, Ag, asr, Bg, bsr, 64, tid);

    for (int i = 0; i < KT; i++) {
        if (i + 2 < KT) CP_WAIT1(); else CP_WAIT0();
        __syncthreads();
        if (i + 2 < KT) {
            char* st = dsm + ((i + 2) % 3) * STAGE_B;
            stage_issue(st, Ag, asr, Bg, bsr, (i + 2) * 64, tid);
        }
        const char* sb = dsm + (i % 3) * STAGE_B;
        compute_buf(sb, sb + TILE_B, wm, wn, lane, acc);
    }
}

// ---------------------------------------------------------------------------
// conversion kernels
// ---------------------------------------------------------------------------
__global__ void __launch_bounds__(256) convcopy_x(
    const float* __restrict__ x, float* __restrict__ out)
{
    size_t i4 = (size_t)blockIdx.x * blockDim.x + threadIdx.x;  // 2097152 total
    float4 a = ((const float4*)x)[i4];
    size_t row = i4 / 128;
    size_t c4  = i4 % 128;
    ((float4*)out)[row * 256 + c4] = a;   // out[..., 0:512] = x
    ((__nv_bfloat162*)g_xb)[i4 * 2]     = __floats2bfloat162_rn(a.x, a.y);
    ((__nv_bfloat162*)g_xb)[i4 * 2 + 1] = __floats2bfloat162_rn(a.z, a.w);
}

__global__ void __launch_bounds__(256) convw_kernel(
    const float* __restrict__ Wq, const float* __restrict__ Wk,
    const float* __restrict__ Wv)
{
    size_t i4 = (size_t)blockIdx.x * blockDim.x + threadIdx.x;  // 196608 total
    int which = (int)(i4 >> 16);
    size_t loc = i4 & 65535;
    const float* src = (which == 0) ? Wq : (which == 1) ? Wk : Wv;
    float4 a = ((const float4*)src)[loc];
    ((__nv_bfloat162*)g_wb)[i4 * 2]     = __floats2bfloat162_rn(a.x, a.y);
    ((__nv_bfloat162*)g_wb)[i4 * 2 + 1] = __floats2bfloat162_rn(a.z, a.w);
}

// ---------------------------------------------------------------------------
// Kernel: q/k/v = x @ W^T + b  (bf16 out)
// ---------------------------------------------------------------------------
__global__ void __launch_bounds__(256, 2) qkv_kernel(
    const float* __restrict__ bq, const float* __restrict__ bk,
    const float* __restrict__ bv)
{
    const int which = blockIdx.z;
    const float* bias = (which == 0) ? bq : (which == 1) ? bk : bv;
    __nv_bfloat16* outp = (which == 0) ? g_qb : (which == 1) ? g_kb : g_vb;

    const int m0 = blockIdx.y * 128;
    const int n0 = blockIdx.x * 128;

    float acc[4][4][4] = {};
    gemm_loop(g_xb + (size_t)m0 * NC, NC,
              g_wb + (size_t)which * 512 * 512 + (size_t)n0 * NC, NC,
              NC / 64, acc);

    const int tid = threadIdx.x, wid = tid >> 5, lane = tid & 31;
    const int gid = lane >> 2, tig = lane & 3;
    const int wm = (wid & 1) * 64, wn = (wid >> 1) * 32;

    #pragma unroll
    for (int mt = 0; mt < 4; mt++) {
        #pragma unroll
        for (int nt = 0; nt < 4; nt++) {
            int m = m0 + wm + mt * 16 + gid;
            int n = n0 + wn + nt * 8 + 2 * tig;
            float b0 = bias[n], b1 = bias[n + 1];
            __nv_bfloat162 h0 = __floats2bfloat162_rn(acc[mt][nt][0] + b0, acc[mt][nt][1] + b1);
            __nv_bfloat162 h1 = __floats2bfloat162_rn(acc[mt][nt][2] + b0, acc[mt][nt][3] + b1);
            *(__nv_bfloat162*)(outp + (size_t)m * NK + n) = h0;
            *(__nv_bfloat162*)(outp + (size_t)(m + 8) * NK + n) = h1;
        }
    }
}

// ---------------------------------------------------------------------------
// Kernel: transpose V (bf16) -> g_vT[b*512+n][s]; tile 32 s x 64 n
// ---------------------------------------------------------------------------
__global__ void __launch_bounds__(256) vtrans_kernel()
{
    __shared__ __nv_bfloat16 ts[32][66];
    const int b  = blockIdx.z;
    const int n0 = blockIdx.x * 64;
    const int s0 = blockIdx.y * 32;
    const int tid = threadIdx.x;

    {
        const int cu = tid & 31;
        const int r0 = tid >> 5;
        #pragma unroll
        for (int j = 0; j < 4; j++) {
            int r = r0 + 8 * j;
            uint32_t v = *(const uint32_t*)(g_vb + ((size_t)(b * NT + s0 + r)) * NK + n0 + cu * 2);
            *(uint32_t*)&ts[r][cu * 2] = v;
        }
    }
    __syncthreads();
    {
        const int cw = tid & 15;
        const int rn0 = tid >> 4;
        #pragma unroll
        for (int j = 0; j < 4; j++) {
            int n = rn0 + 16 * j;
            __nv_bfloat162 p;
            p.x = ts[2 * cw][n];
            p.y = ts[2 * cw + 1][n];
            *(__nv_bfloat162*)(g_vT + ((size_t)(b * NK + n0 + n)) * NT + s0 + 2 * cw) = p;
        }
    }
}

// ---------------------------------------------------------------------------
// Kernel: S = (q @ k^T) * SCALE, lower-triangle tiles only (fp32 out)
// ---------------------------------------------------------------------------
__global__ void __launch_bounds__(256, 2) scores_kernel()
{
    const int b = blockIdx.y;
    int xi = blockIdx.x;
    int qt = (int)((sqrtf(8.0f * xi + 1.0f) - 1.0f) * 0.5f);
    while ((qt + 1) * (qt + 2) / 2 <= xi) qt++;
    while (qt * (qt + 1) / 2 > xi) qt--;
    const int st = xi - qt * (qt + 1) / 2;

    const int m0 = qt * 128;
    const int n0 = st * 128;

    float acc[4][4][4] = {};
    gemm_loop(g_qb + ((size_t)b * NT + m0) * NK, NK,
              g_kb + ((size_t)b * NT + n0) * NK, NK,
              NK / 64, acc);

    float* S = g_S + (size_t)b * NT * NT;
    const int tid = threadIdx.x, wid = tid >> 5, lane = tid & 31;
    const int gid = lane >> 2, tig = lane & 3;
    const int wm = (wid & 1) * 64, wn = (wid >> 1) * 32;

    #pragma unroll
    for (int mt = 0; mt < 4; mt++) {
        #pragma unroll
        for (int nt = 0; nt < 4; nt++) {
            int m = m0 + wm + mt * 16 + gid;
            int n = n0 + wn + nt * 8 + 2 * tig;
            float2 v0 = { acc[mt][nt][0] * SCALE, acc[mt][nt][1] * SCALE };
            float2 v1 = { acc[mt][nt][2] * SCALE, acc[mt][nt][3] * SCALE };
            *(float2*)(S + (size_t)m * NT + n) = v0;
            *(float2*)(S + (size_t)(m + 8) * NT + n) = v1;
        }
    }
}

// ---------------------------------------------------------------------------
// Kernel: column softmax stats (online) + write P (bf16)
// ---------------------------------------------------------------------------
__global__ void __launch_bounds__(256) colstats_kernel()
{
    const int b = blockIdx.y;
    const int cc = threadIdx.x & 31;
    const int rl = threadIdx.x >> 5;     // 0..7
    const int col = blockIdx.x * 32 + cc;
    const float* S = g_S + (size_t)b * NT * NT;
    __nv_bfloat16* P = g_P + (size_t)b * NT * NT;

    __shared__ float redm[8][32];
    __shared__ float redz[8][32];

    const int qstart = (col & ~7) + rl;

    float m = -INFINITY, z = 0.f;
    for (int q = qstart; q < NT; q += 8) {
        if (q >= col) {
            float v = S[(size_t)q * NT + col];
            if (v > m) { z = z * __expf(m - v) + 1.f; m = v; }
            else       { z += __expf(v - m); }
        }
    }
    redm[rl][cc] = m;
    redz[rl][cc] = z;
    __syncthreads();
    if (rl == 0) {
        float M = m;
        #pragma unroll
        for (int r = 1; r < 8; r++) M = fmaxf(M, redm[r][cc]);
        float Z = 0.f;
        #pragma unroll
        for (int r = 0; r < 8; r++) Z += redz[r][cc] * __expf(redm[r][cc] - M);
        redm[0][cc] = M;
        redz[0][cc] = 1.f / Z;
    }
    __syncthreads();
    const float cm  = redm[0][cc];
    const float ciz = redz[0][cc];

    const int qb = (col & ~127) + rl;
    for (int q = qb; q < NT; q += 8) {
        float p = 0.f;
        if (q >= col)
            p = __expf(S[(size_t)q * NT + col] - cm) * ciz;
        P[(size_t)q * NT + col] = __float2bfloat16(p);
    }
}

// ---------------------------------------------------------------------------
// Kernel: attn = P @ V (B = g_vT), triangular k-range
// ---------------------------------------------------------------------------
__global__ void __launch_bounds__(256, 2) attnv_kernel(float* __restrict__ out)
{
    const int b  = blockIdx.z;
    const int qt = gridDim.y - 1 - blockIdx.y;  // big tiles first
    const int n0 = blockIdx.x * 128;
    const int m0 = qt * 128;
    const int KT = 2 * (qt + 1);                // k64 chunks

    float acc[4][4][4] = {};
    gemm_loop(g_P  + ((size_t)b * NT + m0) * NT, NT,
              g_vT + ((size_t)b * NK + n0) * NT, NT,
              KT, acc);

    const int tid = threadIdx.x, wid = tid >> 5, lane = tid & 31;
    const int gid = lane >> 2, tig = lane & 3;
    const int wm = (wid & 1) * 64, wn = (wid >> 1) * 32;

    #pragma unroll
    for (int mt = 0; mt < 4; mt++) {
        #pragma unroll
        for (int nt = 0; nt < 4; nt++) {
            int q = m0 + wm + mt * 16 + gid;
            int n = n0 + wn + nt * 8 + 2 * tig;
            float2 v0 = { acc[mt][nt][0], acc[mt][nt][1] };
            float2 v1 = { acc[mt][nt][2], acc[mt][nt][3] };
            *(float2*)(out + ((size_t)b * NT + q) * 1024 + 512 + n) = v0;
            *(float2*)(out + ((size_t)b * NT + q + 8) * 1024 + 512 + n) = v1;
        }
    }
}

// ---------------------------------------------------------------------------
extern "C" void kernel_launch(void* const* d_in, const int* in_sizes, int n_in,
                              void* d_out, int out_size)
{
    const float* x  = (const float*)d_in[0];
    const float* Wq = (const float*)d_in[1];
    const float* bq = (const float*)d_in[2];
    const float* Wk = (const float*)d_in[3];
    const float* bk = (const float*)d_in[4];
    const float* Wv = (const float*)d_in[5];
    const float* bv = (const float*)d_in[6];
    float* out = (float*)d_out;

    const int dsmem = NSTAGE * STAGE_B;  // 98304 B
    cudaFuncSetAttribute(qkv_kernel,    cudaFuncAttributeMaxDynamicSharedMemorySize, dsmem);
    cudaFuncSetAttribute(scores_kernel, cudaFuncAttributeMaxDynamicSharedMemorySize, dsmem);
    cudaFuncSetAttribute(attnv_kernel,  cudaFuncAttributeMaxDynamicSharedMemorySize, dsmem);

    convcopy_x<<<dim3(8192), 256>>>(x, out);
    convw_kernel<<<dim3(768), 256>>>(Wq, Wk, Wv);
    qkv_kernel<<<dim3(4, 128, 3), 256, dsmem>>>(bq, bk, bv);
    vtrans_kernel<<<dim3(8, 64, 8), 256>>>();
    scores_kernel<<<dim3(136, 8), 256, dsmem>>>();
    colstats_kernel<<<dim3(64, 8), 256>>>();
    attnv_kernel<<<dim3(4, 16, 8), 256, dsmem>>>(out);
}

// round 8
// speedup vs baseline: 1.5162x; 1.0558x over previous
#include <cuda_runtime.h>
#include <cuda_bf16.h>
#include <math.h>
#include <stdint.h>

#define NB 8
#define NT 2048
#define NC 512
#define NK 512
#define SCALE 0.044194173824159216f  // 1/sqrt(512)

// Scratch (device globals: allocation-free per harness rules)
static __device__ __nv_bfloat16 g_xb[(size_t)NB * NT * NC];
static __device__ __nv_bfloat16 g_wb[3 * 512 * 512];
static __device__ __nv_bfloat16 g_qb[(size_t)NB * NT * NK];
static __device__ __nv_bfloat16 g_kb[(size_t)NB * NT * NK];
static __device__ __nv_bfloat16 g_vb[(size_t)NB * NT * NK];
static __device__ __nv_bfloat16 g_vT[(size_t)NB * NK * NT];  // [b*512+n][s]
static __device__ float         g_S [(size_t)NB * NT * NT];  // fp32 scores
static __device__ __nv_bfloat16 g_P [(size_t)NB * NT * NT];  // bf16 probs

// ---------------------------------------------------------------------------
// helpers
// ---------------------------------------------------------------------------
__device__ __forceinline__ void cpa16(void* dst_smem, const void* src) {
    unsigned s = (unsigned)__cvta_generic_to_shared(dst_smem);
    asm volatile("cp.async.cg.shared.global [%0], [%1], 16;\n" :: "r"(s), "l"(src));
}
#define CP_COMMIT() asm volatile("cp.async.commit_group;\n" ::: "memory")
#define CP_WAIT0()  asm volatile("cp.async.wait_group 0;\n" ::: "memory")
#define CP_WAIT1()  asm volatile("cp.async.wait_group 1;\n" ::: "memory")

#define MMA_BF16(c, a, b0, b1)                                              \
    asm volatile(                                                           \
        "mma.sync.aligned.m16n8k16.row.col.f32.bf16.bf16.f32 "              \
        "{%0,%1,%2,%3},{%4,%5,%6,%7},{%8,%9},{%0,%1,%2,%3};\n"              \
        : "+f"((c)[0]), "+f"((c)[1]), "+f"((c)[2]), "+f"((c)[3])            \
        : "r"((a)[0]), "r"((a)[1]), "r"((a)[2]), "r"((a)[3]),               \
          "r"(b0), "r"(b1))

#define LDSM4(r, a)                                                         \
    asm volatile("ldmatrix.sync.aligned.m8n8.x4.shared.b16 "                \
                 "{%0,%1,%2,%3}, [%4];"                                     \
                 : "=r"((r)[0]), "=r"((r)[1]), "=r"((r)[2]), "=r"((r)[3])   \
                 : "r"(a))

// Tile: 128 rows x 64 bf16 = 128B/row, XOR-swizzled in 16B chunks.
#define TILE_B   16384
#define STAGE_B  32768   // A tile + B tile
#define NSTAGE   3

// stage one (A,B) 128x64 bf16 tile pair; 256 threads, 4 chunk-pairs each
__device__ __forceinline__ void stage_issue(
    char* st, const __nv_bfloat16* Ag, size_t asr,
    const __nv_bfloat16* Bg, size_t bsr, int k0, int tid)
{
    #pragma unroll
    for (int j = 0; j < 4; j++) {
        int idx = j * 256 + tid;       // 0..1023
        int row = idx >> 3;
        int ch  = idx & 7;
        int pch = ch ^ (row & 7);      // XOR swizzle (16B units)
        cpa16(st + row * 128 + pch * 16,          Ag + (size_t)row * asr + k0 + ch * 8);
        cpa16(st + TILE_B + row * 128 + pch * 16, Bg + (size_t)row * bsr + k0 + ch * 8);
    }
    CP_COMMIT();
}

// load one k16-group's fragments for a 64x32 warp tile
__device__ __forceinline__ void ld_frags(
    const char* smA, const char* smB, int wm, int wn, int lr, int cg, int kg,
    uint32_t af[4][4], uint32_t bq[2][4])
{
    #pragma unroll
    for (int mt = 0; mt < 4; mt++) {
        int row = wm + mt * 16 + lr;
        int pch = (kg * 2 + cg) ^ (row & 7);
        uint32_t a = (uint32_t)__cvta_generic_to_shared(smA + row * 128 + pch * 16);
        LDSM4(af[mt], a);
    }
    #pragma unroll
    for (int pn = 0; pn < 2; pn++) {
        int row = wn + pn * 16 + lr;
        int pch = (kg * 2 + cg) ^ (row & 7);
        uint32_t a = (uint32_t)__cvta_generic_to_shared(smB + row * 128 + pch * 16);
        LDSM4(bq[pn], a);
    }
}

__device__ __forceinline__ void do_mmas(
    const uint32_t af[4][4], const uint32_t bq[2][4], float acc[4][4][4])
{
    #pragma unroll
    for (int mt = 0; mt < 4; mt++) {
        #pragma unroll
        for (int nt = 0; nt < 4; nt++) {
            const uint32_t* bp = bq[nt >> 1];
            uint32_t b0 = (nt & 1) ? bp[1] : bp[0];
            uint32_t b1 = (nt & 1) ? bp[3] : bp[2];
            MMA_BF16(acc[mt][nt], af[mt], b0, b1);
        }
    }
}

// compute one 128x128x64 buffer: 4 k16 steps, frag double-buffered
__device__ __forceinline__ void compute_buf(
    const char* smA, const char* smB,
    int wm, int wn, int lane, float acc[4][4][4])
{
    const int lr = lane & 15;      // row-within-16
    const int cg = lane >> 4;      // 0/1: which 16B chunk of the k16 group
    uint32_t afA[4][4], bqA[2][4], afB[4][4], bqB[2][4];

    ld_frags(smA, smB, wm, wn, lr, cg, 0, afA, bqA);
    ld_frags(smA, smB, wm, wn, lr, cg, 1, afB, bqB);
    do_mmas(afA, bqA, acc);
    ld_frags(smA, smB, wm, wn, lr, cg, 2, afA, bqA);
    do_mmas(afB, bqB, acc);
    ld_frags(smA, smB, wm, wn, lr, cg, 3, afB, bqB);
    do_mmas(afA, bqA, acc);
    do_mmas(afB, bqB, acc);
}

// 3-stage pipelined NT GEMM (both operands k-major bf16). KT in k64 units.
__device__ __forceinline__ void gemm_loop(
    const __nv_bfloat16* Ag, size_t asr,
    const __nv_bfloat16* Bg, size_t bsr,
    int KT, float acc[4][4][4])
{
    extern __shared__ char dsm[];
    const int tid  = threadIdx.x;
    const int wid  = tid >> 5;
    const int lane = tid & 31;
    const int wm   = (wid & 1) * 64;
    const int wn   = (wid >> 1) * 32;

    stage_issue(dsm,           Ag, asr, Bg, bsr, 0,  tid);
    stage_issue(dsm + STAGE_B, Ag, asr, Bg, bsr, 64, tid);

    for (int i = 0; i < KT; i++) {
        if (i + 2 < KT) CP_WAIT1(); else CP_WAIT0();
        __syncthreads();
        if (i + 2 < KT) {
            char* st = dsm + ((i + 2) % 3) * STAGE_B;
            stage_issue(st, Ag, asr, Bg, bsr, (i + 2) * 64, tid);
        }
        const char* sb = dsm + (i % 3) * STAGE_B;
        compute_buf(sb, sb + TILE_B, wm, wn, lane, acc);
    }
}

// ---------------------------------------------------------------------------
// conversion kernels
// ---------------------------------------------------------------------------
__global__ void __launch_bounds__(256) convcopy_x(
    const float* __restrict__ x, float* __restrict__ out)
{
    size_t i4 = (size_t)blockIdx.x * blockDim.x + threadIdx.x;  // 2097152 total
    float4 a = ((const float4*)x)[i4];
    size_t row = i4 / 128;
    size_t c4  = i4 % 128;
    ((float4*)out)[row * 256 + c4] = a;   // out[..., 0:512] = x
    ((__nv_bfloat162*)g_xb)[i4 * 2]     = __floats2bfloat162_rn(a.x, a.y);
    ((__nv_bfloat162*)g_xb)[i4 * 2 + 1] = __floats2bfloat162_rn(a.z, a.w);
}

__global__ void __launch_bounds__(256) convw_kernel(
    const float* __restrict__ Wq, const float* __restrict__ Wk,
    const float* __restrict__ Wv)
{
    size_t i4 = (size_t)blockIdx.x * blockDim.x + threadIdx.x;  // 196608 total
    int which = (int)(i4 >> 16);
    size_t loc = i4 & 65535;
    const float* src = (which == 0) ? Wq : (which == 1) ? Wk : Wv;
    float4 a = ((const float4*)src)[loc];
    ((__nv_bfloat162*)g_wb)[i4 * 2]     = __floats2bfloat162_rn(a.x, a.y);
    ((__nv_bfloat162*)g_wb)[i4 * 2 + 1] = __floats2bfloat162_rn(a.z, a.w);
}

// ---------------------------------------------------------------------------
// Kernel: q/k/v = x @ W^T + b  (bf16 out)
// ---------------------------------------------------------------------------
__global__ void __launch_bounds__(256, 2) qkv_kernel(
    const float* __restrict__ bq, const float* __restrict__ bk,
    const float* __restrict__ bv)
{
    const int which = blockIdx.z;
    const float* bias = (which == 0) ? bq : (which == 1) ? bk : bv;
    __nv_bfloat16* outp = (which == 0) ? g_qb : (which == 1) ? g_kb : g_vb;

    const int m0 = blockIdx.y * 128;
    const int n0 = blockIdx.x * 128;

    float acc[4][4][4] = {};
    gemm_loop(g_xb + (size_t)m0 * NC, NC,
              g_wb + (size_t)which * 512 * 512 + (size_t)n0 * NC, NC,
              NC / 64, acc);

    const int tid = threadIdx.x, wid = tid >> 5, lane = tid & 31;
    const int gid = lane >> 2, tig = lane & 3;
    const int wm = (wid & 1) * 64, wn = (wid >> 1) * 32;

    #pragma unroll
    for (int mt = 0; mt < 4; mt++) {
        #pragma unroll
        for (int nt = 0; nt < 4; nt++) {
            int m = m0 + wm + mt * 16 + gid;
            int n = n0 + wn + nt * 8 + 2 * tig;
            float b0 = bias[n], b1 = bias[n + 1];
            __nv_bfloat162 h0 = __floats2bfloat162_rn(acc[mt][nt][0] + b0, acc[mt][nt][1] + b1);
            __nv_bfloat162 h1 = __floats2bfloat162_rn(acc[mt][nt][2] + b0, acc[mt][nt][3] + b1);
            *(__nv_bfloat162*)(outp + (size_t)m * NK + n) = h0;
            *(__nv_bfloat162*)(outp + (size_t)(m + 8) * NK + n) = h1;
        }
    }
}

// ---------------------------------------------------------------------------
// Kernel: transpose V (bf16) -> g_vT[b*512+n][s]; tile 32 s x 64 n
// ---------------------------------------------------------------------------
__global__ void __launch_bounds__(256) vtrans_kernel()
{
    __shared__ __nv_bfloat16 ts[32][66];
    const int b  = blockIdx.z;
    const int n0 = blockIdx.x * 64;
    const int s0 = blockIdx.y * 32;
    const int tid = threadIdx.x;

    {
        const int cu = tid & 31;
        const int r0 = tid >> 5;
        #pragma unroll
        for (int j = 0; j < 4; j++) {
            int r = r0 + 8 * j;
            uint32_t v = *(const uint32_t*)(g_vb + ((size_t)(b * NT + s0 + r)) * NK + n0 + cu * 2);
            *(uint32_t*)&ts[r][cu * 2] = v;
        }
    }
    __syncthreads();
    {
        const int cw = tid & 15;
        const int rn0 = tid >> 4;
        #pragma unroll
        for (int j = 0; j < 4; j++) {
            int n = rn0 + 16 * j;
            __nv_bfloat162 p;
            p.x = ts[2 * cw][n];
            p.y = ts[2 * cw + 1][n];
            *(__nv_bfloat162*)(g_vT + ((size_t)(b * NK + n0 + n)) * NT + s0 + 2 * cw) = p;
        }
    }
}

// ---------------------------------------------------------------------------
// Kernel: S = (q @ k^T) * SCALE, lower-triangle tiles only (fp32 out)
// ---------------------------------------------------------------------------
__global__ void __launch_bounds__(256, 2) scores_kernel()
{
    const int b = blockIdx.y;
    int xi = blockIdx.x;
    int qt = (int)((sqrtf(8.0f * xi + 1.0f) - 1.0f) * 0.5f);
    while ((qt + 1) * (qt + 2) / 2 <= xi) qt++;
    while (qt * (qt + 1) / 2 > xi) qt--;
    const int st = xi - qt * (qt + 1) / 2;

    const int m0 = qt * 128;
    const int n0 = st * 128;

    float acc[4][4][4] = {};
    gemm_loop(g_qb + ((size_t)b * NT + m0) * NK, NK,
              g_kb + ((size_t)b * NT + n0) * NK, NK,
              NK / 64, acc);

    float* S = g_S + (size_t)b * NT * NT;
    const int tid = threadIdx.x, wid = tid >> 5, lane = tid & 31;
    const int gid = lane >> 2, tig = lane & 3;
    const int wm = (wid & 1) * 64, wn = (wid >> 1) * 32;

    #pragma unroll
    for (int mt = 0; mt < 4; mt++) {
        #pragma unroll
        for (int nt = 0; nt < 4; nt++) {
            int m = m0 + wm + mt * 16 + gid;
            int n = n0 + wn + nt * 8 + 2 * tig;
            float2 v0 = { acc[mt][nt][0] * SCALE, acc[mt][nt][1] * SCALE };
            float2 v1 = { acc[mt][nt][2] * SCALE, acc[mt][nt][3] * SCALE };
            *(float2*)(S + (size_t)m * NT + n) = v0;
            *(float2*)(S + (size_t)(m + 8) * NT + n) = v1;
        }
    }
}

// ---------------------------------------------------------------------------
// Kernel: column softmax stats (online) + write P (bf16)
// ---------------------------------------------------------------------------
__global__ void __launch_bounds__(256) colstats_kernel()
{
    const int b = blockIdx.y;
    const int cc = threadIdx.x & 31;
    const int rl = threadIdx.x >> 5;     // 0..7
    const int col = blockIdx.x * 32 + cc;
    const float* S = g_S + (size_t)b * NT * NT;
    __nv_bfloat16* P = g_P + (size_t)b * NT * NT;

    __shared__ float redm[8][32];
    __shared__ float redz[8][32];

    const int qstart = (col & ~7) + rl;

    float m = -INFINITY, z = 0.f;
    for (int q = qstart; q < NT; q += 8) {
        if (q >= col) {
            float v = S[(size_t)q * NT + col];
            if (v > m) { z = z * __expf(m - v) + 1.f; m = v; }
            else       { z += __expf(v - m); }
        }
    }
    redm[rl][cc] = m;
    redz[rl][cc] = z;
    __syncthreads();
    if (rl == 0) {
        float M = m;
        #pragma unroll
        for (int r = 1; r < 8; r++) M = fmaxf(M, redm[r][cc]);
        float Z = 0.f;
        #pragma unroll
        for (int r = 0; r < 8; r++) Z += redz[r][cc] * __expf(redm[r][cc] - M);
        redm[0][cc] = M;
        redz[0][cc] = 1.f / Z;
    }
    __syncthreads();
    const float cm  = redm[0][cc];
    const float ciz = redz[0][cc];

    const int qb = (col & ~127) + rl;
    for (int q = qb; q < NT; q += 8) {
        float p = 0.f;
        if (q >= col)
            p = __expf(S[(size_t)q * NT + col] - cm) * ciz;
        P[(size_t)q * NT + col] = __float2bfloat16(p);
    }
}

// ---------------------------------------------------------------------------
// Kernel: attn = P @ V (B = g_vT), triangular k-range
// ---------------------------------------------------------------------------
__global__ void __launch_bounds__(256, 2) attnv_kernel(float* __restrict__ out)
{
    const int b  = blockIdx.z;
    const int qt = gridDim.y - 1 - blockIdx.y;  // big tiles first
    const int n0 = blockIdx.x * 128;
    const int m0 = qt * 128;
    const int KT = 2 * (qt + 1);                // k64 chunks

    float acc[4][4][4] = {};
    gemm_loop(g_P  + ((size_t)b * NT + m0) * NT, NT,
              g_vT + ((size_t)b * NK + n0) * NT, NT,
              KT, acc);

    const int tid = threadIdx.x, wid = tid >> 5, lane = tid & 31;
    const int gid = lane >> 2, tig = lane & 3;
    const int wm = (wid & 1) * 64, wn = (wid >> 1) * 32;

    #pragma unroll
    for (int mt = 0; mt < 4; mt++) {
        #pragma unroll
        for (int nt = 0; nt < 4; nt++) {
            int q = m0 + wm + mt * 16 + gid;
            int n = n0 + wn + nt * 8 + 2 * tig;
            float2 v0 = { acc[mt][nt][0], acc[mt][nt][1] };
            float2 v1 = { acc[mt][nt][2], acc[mt][nt][3] };
            *(float2*)(out + ((size_t)b * NT + q) * 1024 + 512 + n) = v0;
            *(float2*)(out + ((size_t)b * NT + q + 8) * 1024 + 512 + n) = v1;
        }
    }
}

// ---------------------------------------------------------------------------
extern "C" void kernel_launch(void* const* d_in, const int* in_sizes, int n_in,
                              void* d_out, int out_size)
{
    const float* x  = (const float*)d_in[0];
    const float* Wq = (const float*)d_in[1];
    const float* bq = (const float*)d_in[2];
    const float* Wk = (const float*)d_in[3];
    const float* bk = (const float*)d_in[4];
    const float* Wv = (const float*)d_in[5];
    const float* bv = (const float*)d_in[6];
    float* out = (float*)d_out;

    const int dsmem = NSTAGE * STAGE_B;  // 98304 B
    cudaFuncSetAttribute(qkv_kernel,    cudaFuncAttributeMaxDynamicSharedMemorySize, dsmem);
    cudaFuncSetAttribute(scores_kernel, cudaFuncAttributeMaxDynamicSharedMemorySize, dsmem);
    cudaFuncSetAttribute(attnv_kernel,  cudaFuncAttributeMaxDynamicSharedMemorySize, dsmem);

    convcopy_x<<<dim3(8192), 256>>>(x, out);
    convw_kernel<<<dim3(768), 256>>>(Wq, Wk, Wv);
    qkv_kernel<<<dim3(4, 128, 3), 256, dsmem>>>(bq, bk, bv);
    vtrans_kernel<<<dim3(8, 64, 8), 256>>>();
    scores_kernel<<<dim3(136, 8), 256, dsmem>>>();
    colstats_kernel<<<dim3(64, 8), 256>>>();
    attnv_kernel<<<dim3(4, 16, 8), 256, dsmem>>>(out);
}